// round 2
// baseline (speedup 1.0000x reference)
#include <cuda_runtime.h>
#include <cstdint>

typedef unsigned long long ull;

// Problem constants
//   x: (8, 256, 128, 128) fp32
//   out: (8, 256, 64, 64) fp32
//   K=5 (25 taps), S=2, encoder conv 3x3 stride2 pad1 on compressed(64ch)

#define NCP   128      // channel pairs (256/2)
#define XN    1122     // 17*66  logits x-tile entries (ull = {c0,c1})
#define EVN   374      // 11*34  aggregate even-col entries
#define ODN   363      // 11*33  aggregate odd-col entries

// ---- persistent device scratch (no runtime allocation allowed) ----
// fused weights: [cp][tap][kk] float4 = {w[2kk][c0], w[2kk][c1], w[2kk+1][c0], w[2kk+1][c1]}
__device__ float4 g_W2[NCP * 9 * 13];
__device__ float  g_btap[9 * 32];    // per-tap bias (b_comp routed through encoder), k-padded to 32
__device__ float  g_bk[32];          // b_enc * exp(p)
__device__ float  g_mask[8 * 25 * 64 * 64];   // softmaxed masks, [b][k][h][w]

__device__ __forceinline__ ull pack2(float a, float b) {
    ull r; asm("mov.b64 %0, {%1, %2};" : "=l"(r) : "f"(a), "f"(b)); return r;
}
__device__ __forceinline__ void unpack2(ull v, float& a, float& b) {
    asm("mov.b64 {%0, %1}, %2;" : "=f"(a), "=f"(b) : "l"(v));
}
// packed dual-FMA: d.lo += a.lo*b.lo ; d.hi += a.hi*b.hi   (Blackwell f32x2 pipe, 2x FFMA rate)
#define FMA2(d, a, b) asm("fma.rn.f32x2 %0, %1, %2, %0;" : "+l"(d) : "l"(a), "l"(b))

// ============================================================================
// Kernel 1: fuse compressor+encoder weights. 225 blocks (k,tap) x 256 threads (c).
// ============================================================================
__global__ void prep_kernel(const float* __restrict__ w_comp, const float* __restrict__ b_comp,
                            const float* __restrict__ w_enc, const float* __restrict__ b_enc,
                            const float* __restrict__ power_p) {
    int k = blockIdx.x / 9, tap = blockIdx.x % 9;
    int c = threadIdx.x;
    __shared__ float we[64];
    float expP = __expf(power_p[0]);
    if (c < 64) we[c] = w_enc[(k * 64 + c) * 9 + tap];
    __syncthreads();
    float s = 0.f;
#pragma unroll 8
    for (int cc = 0; cc < 64; cc++) s += we[cc] * w_comp[cc * 256 + c];
    s *= expP;
    float* W2f = (float*)g_W2;
    int cp = c >> 1, kk = k >> 1;
    W2f[((cp * 9 + tap) * 13 + kk) * 4 + (k & 1) * 2 + (c & 1)] = s;
    // zero the k=25 pad lanes (kk=12, slots 2/3)
    if (k == 0 && c < 128) {
        W2f[((c * 9 + tap) * 13 + 12) * 4 + 2] = 0.f;
        W2f[((c * 9 + tap) * 13 + 12) * 4 + 3] = 0.f;
    }
    if (c == 0) {
        float bs = 0.f;
        for (int cc = 0; cc < 64; cc++) bs += we[cc] * b_comp[cc];
        g_btap[tap * 32 + k] = bs * expP;
        if (tap == 0) g_bk[k] = b_enc[k] * expP;
    }
}

// ============================================================================
// Kernel 2: fused 3x3-stride2 logit conv (256ch -> 25k) + softmax -> g_mask.
// grid 128 blocks: [b(8)][tile(16)]; tile = 32w x 8h, 128 threads, 2 px/thread.
// Channel-pair f32x2 packing; weights via broadcast LDS.128.
// ============================================================================
__global__ __launch_bounds__(128, 1) void logits_kernel(const float* __restrict__ x) {
    int bid = blockIdx.x;
    int b  = bid >> 4;
    int t  = bid & 15;
    int w0 = (t & 1) * 32;
    int h0 = (t >> 1) * 8;
    int tid = threadIdx.x;
    int lw = tid & 31;
    int lh = tid >> 5;          // 0..3 ; pixels (h0+lh, w) and (h0+lh+4, w)

    __shared__ ull    xs[XN];        // [17 rows][66 cols] of {c_even, c_odd}
    __shared__ float4 ws[117];       // [tap 9][kk 13]
    __shared__ float  btap_s[288];
    __shared__ float  bk_s[32];

    for (int i = tid; i < 288; i += 128) btap_s[i] = g_btap[i];
    if (tid < 32) bk_s[tid] = g_bk[tid];

    ull acc0[26], acc1[26];
#pragma unroll
    for (int i = 0; i < 26; i++) { acc0[i] = 0ull; acc1[i] = 0ull; }

    const float* xb = x + (size_t)b * 256 * 16384;
    float pf0[9], pf1[9];
    float4 wpf = make_float4(0.f, 0.f, 0.f, 0.f);

    auto prefetch = [&](int cp) {
        const float* xc = xb + (size_t)(2 * cp) * 16384;
#pragma unroll
        for (int it = 0; it < 9; it++) {
            int idx = tid + it * 128;
            float v0 = 0.f, v1 = 0.f;
            if (idx < XN) {
                int r   = idx / 66;
                int col = idx - r * 66;
                int gr = 2 * h0 - 1 + r;
                int gc = 2 * w0 - 1 + col;
                if (gr >= 0 && gc >= 0 && gc < 128) {
                    const float* p = xc + (gr << 7) + gc;
                    v0 = p[0];
                    v1 = p[16384];
                }
            }
            pf0[it] = v0; pf1[it] = v1;
        }
        if (tid < 117) wpf = g_W2[cp * 117 + tid];
    };
    auto commit = [&]() {
#pragma unroll
        for (int it = 0; it < 9; it++) {
            int idx = tid + it * 128;
            if (idx < XN) xs[idx] = pack2(pf0[it], pf1[it]);
        }
        if (tid < 117) ws[tid] = wpf;
    };

    prefetch(0);
#pragma unroll 1
    for (int cp = 0; cp < NCP; cp++) {
        __syncthreads();
        commit();
        __syncthreads();
        if (cp < NCP - 1) prefetch(cp + 1);   // LDG latency hides under FFMA block below
#pragma unroll
        for (int tap = 0; tap < 9; tap++) {
            int dy = tap / 3, dx = tap % 3;
            ull xv0 = xs[(2 * lh +     dy) * 66 + 2 * lw + dx];
            ull xv1 = xs[(2 * lh + 8 + dy) * 66 + 2 * lw + dx];
            const ulonglong2* wp = (const ulonglong2*)(ws + tap * 13);
#pragma unroll
            for (int kk = 0; kk < 13; kk++) {
                ulonglong2 wv = wp[kk];   // {w[2kk] pair, w[2kk+1] pair}
                FMA2(acc0[2 * kk],     wv.x, xv0);
                FMA2(acc0[2 * kk + 1], wv.y, xv0);
                FMA2(acc1[2 * kk],     wv.x, xv1);
                FMA2(acc1[2 * kk + 1], wv.y, xv1);
            }
        }
    }

    // epilogue: reduce pairs, border bias, softmax, store mask
    auto do_px = [&](ull (&acc)[26], int h) {
        int w = w0 + lw;
        float logit[25];
#pragma unroll
        for (int k = 0; k < 25; k++) {
            float a, c2;
            unpack2(acc[k], a, c2);
            logit[k] = a + c2 + bk_s[k];
        }
#pragma unroll
        for (int tap = 0; tap < 9; tap++) {
            int dy = tap / 3, dx = tap % 3;
            bool inb = (2 * h - 1 + dy >= 0) && (2 * w - 1 + dx >= 0) && (2 * w - 1 + dx < 128);
            if (inb) {
#pragma unroll
                for (int k = 0; k < 25; k++) logit[k] += btap_s[tap * 32 + k];
            }
        }
        float mx = logit[0];
#pragma unroll
        for (int k = 1; k < 25; k++) mx = fmaxf(mx, logit[k]);
        float sum = 0.f;
#pragma unroll
        for (int k = 0; k < 25; k++) { logit[k] = __expf(logit[k] - mx); sum += logit[k]; }
        float inv = 1.f / sum;
#pragma unroll
        for (int k = 0; k < 25; k++)
            g_mask[(((b * 25 + k) * 64) + h) * 64 + w] = logit[k] * inv;
    };
    do_px(acc0, h0 + lh);
    do_px(acc1, h0 + lh + 4);
}

// ============================================================================
// Kernel 3: 25-tap stride-2 weighted gather. grid 256: [b(8)][tile(32)];
// tile = 32w x 4h, 128 threads, 1 px/thread, loop 128 channel-pairs.
// De-strided even/odd smem layout -> conflict-free lane-contiguous LDS.64.
// ============================================================================
__global__ __launch_bounds__(128, 1) void aggregate_kernel(const float* __restrict__ x,
                                                           float* __restrict__ out) {
    int bid = blockIdx.x;
    int b  = bid >> 5;
    int t  = bid & 31;
    int w0 = (t & 1) * 32;
    int h0 = (t >> 1) * 4;
    int tid = threadIdx.x;
    int lw = tid & 31;
    int lh = tid >> 5;
    int h = h0 + lh, w = w0 + lw;

    __shared__ ull ev[EVN];   // [11 rows][34 even-cols] of {c0,c1}
    __shared__ ull od[ODN];   // [11 rows][33 odd-cols]

    ull m2[25];
#pragma unroll
    for (int k = 0; k < 25; k++) {
        float m = g_mask[(((b * 25 + k) * 64) + h) * 64 + w];
        m2[k] = pack2(m, m);
    }

    const float* xb = x + (size_t)b * 256 * 16384;
    float pa0[6], pa1[6];

    auto prefetch = [&](int cp) {
        const float* xc = xb + (size_t)(2 * cp) * 16384;
#pragma unroll
        for (int it = 0; it < 6; it++) {
            int idx = tid + it * 128;
            float v0 = 0.f, v1 = 0.f;
            if (idx < EVN + ODN) {
                int r, gcol;
                if (idx < EVN) { r = idx / 34; gcol = 2 * w0 - 2 + 2 * (idx - r * 34); }
                else           { int j = idx - EVN; r = j / 33; gcol = 2 * w0 - 1 + 2 * (j - r * 33); }
                int gr = 2 * h0 - 2 + r;
                if (gr >= 0 && gr < 128 && gcol >= 0 && gcol < 128) {
                    const float* p = xc + (gr << 7) + gcol;
                    v0 = p[0];
                    v1 = p[16384];
                }
            }
            pa0[it] = v0; pa1[it] = v1;
        }
    };
    auto commit = [&]() {
#pragma unroll
        for (int it = 0; it < 6; it++) {
            int idx = tid + it * 128;
            if (idx < EVN)            ev[idx]       = pack2(pa0[it], pa1[it]);
            else if (idx < EVN + ODN) od[idx - EVN] = pack2(pa0[it], pa1[it]);
        }
    };

    float* ob = out + (((size_t)b * 256) << 12);
    prefetch(0);
#pragma unroll 1
    for (int cp = 0; cp < NCP; cp++) {
        __syncthreads();
        commit();
        __syncthreads();
        if (cp < NCP - 1) prefetch(cp + 1);

        ull acc_a = 0ull, acc_b = 0ull;   // split chains (latency)
#pragma unroll
        for (int di = 0; di < 5; di++) {
            int lr = 2 * lh + di;
            ull x0 = ev[lr * 34 + lw];
            ull x1 = od[lr * 33 + lw];
            ull x2 = ev[lr * 34 + lw + 1];
            ull x3 = od[lr * 33 + lw + 1];
            ull x4 = ev[lr * 34 + lw + 2];
            FMA2(acc_a, m2[di * 5 + 0], x0);
            FMA2(acc_b, m2[di * 5 + 1], x1);
            FMA2(acc_a, m2[di * 5 + 2], x2);
            FMA2(acc_b, m2[di * 5 + 3], x3);
            FMA2(acc_a, m2[di * 5 + 4], x4);
        }
        float a0, a1, b0, b1;
        unpack2(acc_a, a0, a1);
        unpack2(acc_b, b0, b1);
        float* po = ob + (((size_t)(2 * cp)) << 12) + (h << 6) + w;
        po[0]    = a0 + b0;
        po[4096] = a1 + b1;
    }
}

// ============================================================================
extern "C" void kernel_launch(void* const* d_in, const int* in_sizes, int n_in,
                              void* d_out, int out_size) {
    const float* x       = (const float*)d_in[0];
    const float* w_comp  = (const float*)d_in[1];
    const float* b_comp  = (const float*)d_in[2];
    const float* w_enc   = (const float*)d_in[3];
    const float* b_enc   = (const float*)d_in[4];
    const float* power_p = (const float*)d_in[5];
    float* out = (float*)d_out;

    prep_kernel<<<225, 256>>>(w_comp, b_comp, w_enc, b_enc, power_p);
    logits_kernel<<<128, 128>>>(x);
    aggregate_kernel<<<256, 128>>>(x, out);
}

// round 4
// speedup vs baseline: 1.5781x; 1.5781x over previous
#include <cuda_runtime.h>
#include <cstdint>

typedef unsigned long long ull;

// Problem: x (8,256,128,128) f32 -> out (8,256,64,64) f32
// CARAFE downsample: 1x1 conv(256->64) . 3x3 s2 conv(64->25) . softmax . 5x5 s2 gather

#define NCP   128        // channel pairs
// logits tile: 32w x 8h px, region 17 rows x 66 cols, even/odd local-col planes
#define XEV   561        // 17*33
#define XOD   544        // 17*32
#define XNT   1105       // XEV+XOD
// aggregate tile: 32w x 4h px, region 11 rows x 67 cols, even/odd gmem-col planes
#define AEV   374        // 11*34
#define AOD   363        // 11*33
#define ANT   737

// ---- persistent device scratch ----
__device__ float4 g_W2[NCP * 9 * 13];           // [cp][tap][kk]{w2k_c0,w2k_c1,w2k1_c0,w2k1_c1}
__device__ float  g_btap[9 * 32];               // per-tap bias (b_comp through encoder)
__device__ float  g_bk[32];                     // b_enc * exp(p)
__device__ float  g_part[2 * 8 * 25 * 64 * 64]; // partial logits per channel-chunk

__device__ __forceinline__ ull pack2(float a, float b) {
    ull r; asm("mov.b64 %0, {%1, %2};" : "=l"(r) : "f"(a), "f"(b)); return r;
}
__device__ __forceinline__ void unpack2(ull v, float& a, float& b) {
    asm("mov.b64 {%0, %1}, %2;" : "=f"(a), "=f"(b) : "l"(v));
}
#define FMA2(d, a, b) asm("fma.rn.f32x2 %0, %1, %2, %0;" : "+l"(d) : "l"(a), "l"(b))

__device__ __forceinline__ uint32_t smem_u32(const void* p) {
    return (uint32_t)__cvta_generic_to_shared(p);
}
__device__ __forceinline__ void cpa4(uint32_t dst, const float* src) {
    asm volatile("cp.async.ca.shared.global [%0], [%1], 4;" :: "r"(dst), "l"(src));
}
__device__ __forceinline__ void cpa16(uint32_t dst, const void* src) {
    asm volatile("cp.async.ca.shared.global [%0], [%1], 16;" :: "r"(dst), "l"(src));
}
#define CP_COMMIT() asm volatile("cp.async.commit_group;")
template<int N> __device__ __forceinline__ void cp_wait() {
    asm volatile("cp.async.wait_group %0;" :: "n"(N));
}

// ============================================================================
// Kernel 1: fuse compressor+encoder weights. 225 blocks (k,tap) x 256 threads.
// ============================================================================
__global__ void prep_kernel(const float* __restrict__ w_comp, const float* __restrict__ b_comp,
                            const float* __restrict__ w_enc, const float* __restrict__ b_enc,
                            const float* __restrict__ power_p) {
    int k = blockIdx.x / 9, tap = blockIdx.x % 9;
    int c = threadIdx.x;
    __shared__ float we[64];
    float expP = __expf(power_p[0]);
    if (c < 64) we[c] = w_enc[(k * 64 + c) * 9 + tap];
    __syncthreads();
    float s = 0.f;
#pragma unroll 8
    for (int cc = 0; cc < 64; cc++) s += we[cc] * w_comp[cc * 256 + c];
    s *= expP;
    float* W2f = (float*)g_W2;
    int cp = c >> 1, kk = k >> 1;
    W2f[((cp * 9 + tap) * 13 + kk) * 4 + (k & 1) * 2 + (c & 1)] = s;
    if (k == 0 && c < 128) {  // zero k=25 pad lanes
        W2f[((c * 9 + tap) * 13 + 12) * 4 + 2] = 0.f;
        W2f[((c * 9 + tap) * 13 + 12) * 4 + 3] = 0.f;
    }
    if (c == 0) {
        float bs = 0.f;
        for (int cc = 0; cc < 64; cc++) bs += we[cc] * b_comp[cc];
        g_btap[tap * 32 + k] = bs * expP;
        if (tap == 0) g_bk[k] = b_enc[k] * expP;
    }
}

// ============================================================================
// Kernel 2: fused 3x3-s2 logit conv, channel-split 2-way. 256 blocks x 128 thr.
// 2 px/thread, channel-pair f32x2, cp.async 2-stage pipeline.
// ============================================================================
__global__ __launch_bounds__(128) void logits_kernel(const float* __restrict__ x) {
    int bid = blockIdx.x;
    int chunk = bid & 1;
    int tile  = (bid >> 1) & 15;
    int b     = bid >> 5;
    int w0 = (tile & 1) * 32;
    int h0 = (tile >> 1) * 8;
    int tid = threadIdx.x;
    int lw = tid & 31;
    int lh = tid >> 5;

    __shared__ ull    xs[2][XNT];      // [ev 561 | od 544], ull = {c_even, c_odd}
    __shared__ float4 ws[2][117];

    // zero both stages once: OOB slots stay zero, valid slots are overwritten each fill
    for (int i = tid; i < XNT; i += 128) { xs[0][i] = 0ull; xs[1][i] = 0ull; }

    // ---- one-time per-thread fill addressing ----
    int      goff[9];
    bool     vld[9];
    uint32_t sdst0[9], sdst1[9];
    uint32_t xs0 = smem_u32(&xs[0][0]), xs1 = smem_u32(&xs[1][0]);
#pragma unroll
    for (int it = 0; it < 9; it++) {
        int idx = tid + it * 128;
        int gr = 0, gc = 0;
        bool ok = idx < XNT;
        if (ok) {
            int r, lc;
            if (idx < XEV) { r = idx / 33; lc = 2 * (idx - 33 * r); }
            else           { int j = idx - XEV; r = j / 32; lc = 2 * (j - 32 * r) + 1; }
            gr = 2 * h0 - 1 + r;
            gc = 2 * w0 - 1 + lc;
            ok = (gr >= 0) && (gc >= 0) && (gc < 128);   // right-edge bound restored
        }
        vld[it]  = ok;
        goff[it] = ok ? ((gr << 7) + gc) : 0;
        uint32_t off = ok ? (uint32_t)idx * 8 : 0u;
        sdst0[it] = xs0 + off;
        sdst1[it] = xs1 + off;
    }
    uint32_t wdst0 = smem_u32(&ws[0][0]) + (uint32_t)tid * 16;
    uint32_t wdst1 = smem_u32(&ws[1][0]) + (uint32_t)tid * 16;

    ull acc0[26], acc1[26];
#pragma unroll
    for (int i = 0; i < 26; i++) { acc0[i] = 0ull; acc1[i] = 0ull; }

    const float* xb = x + (size_t)b * 256 * 16384;
    int cp0 = chunk * 64;

    auto fill = [&](int s, int cp) {
        const float* xc = xb + (size_t)(2 * cp) * 16384;
#pragma unroll
        for (int it = 0; it < 9; it++) {
            if (vld[it]) {
                uint32_t d = s ? sdst1[it] : sdst0[it];
                const float* p = xc + goff[it];
                cpa4(d,     p);
                cpa4(d + 4, p + 16384);
            }
        }
        if (tid < 117) cpa16(s ? wdst1 : wdst0, &g_W2[cp * 117 + tid]);
        CP_COMMIT();
    };

    __syncthreads();      // zeroing visible before first consume
    fill(0, cp0);
#pragma unroll 1
    for (int i = 0; i < 64; i++) {
        int s = i & 1;
        if (i + 1 < 64) { fill(s ^ 1, cp0 + i + 1); cp_wait<1>(); }
        else            { cp_wait<0>(); }
        __syncthreads();
#pragma unroll
        for (int dy = 0; dy < 3; dy++) {
#pragma unroll
            for (int dx = 0; dx < 3; dx++) {
                int tap = dy * 3 + dx;
                int r0 = 2 * lh + dy, r1 = r0 + 8;
                int i0, i1;
                if (dx == 0)      { i0 = r0 * 33 + lw;           i1 = r1 * 33 + lw; }
                else if (dx == 1) { i0 = XEV + r0 * 32 + lw;     i1 = XEV + r1 * 32 + lw; }
                else              { i0 = r0 * 33 + lw + 1;       i1 = r1 * 33 + lw + 1; }
                ull xv0 = xs[s][i0];
                ull xv1 = xs[s][i1];
                const ulonglong2* wp = (const ulonglong2*)(&ws[s][tap * 13]);
#pragma unroll
                for (int kk = 0; kk < 13; kk++) {
                    ulonglong2 wv = wp[kk];
                    FMA2(acc0[2 * kk],     wv.x, xv0);
                    FMA2(acc0[2 * kk + 1], wv.y, xv0);
                    FMA2(acc1[2 * kk],     wv.x, xv1);
                    FMA2(acc1[2 * kk + 1], wv.y, xv1);
                }
            }
        }
        __syncthreads();
    }

    // store partial logits (no bias; aggregate adds bias + softmax)
    float* part = g_part + (size_t)chunk * (8 * 25 * 4096);
    int w = w0 + lw;
    int hA = h0 + lh, hB = h0 + lh + 4;
#pragma unroll
    for (int k = 0; k < 25; k++) {
        float a, c2;
        unpack2(acc0[k], a, c2);
        part[(((b * 25 + k) << 12)) + (hA << 6) + w] = a + c2;
        unpack2(acc1[k], a, c2);
        part[(((b * 25 + k) << 12)) + (hB << 6) + w] = a + c2;
    }
}

// ============================================================================
// Kernel 3: softmax prologue + 25-tap s2 gather. 256 blocks x 128 threads,
// 1 px/thread, cp.async 2-stage, even/odd-col conflict-free smem planes.
// ============================================================================
__global__ __launch_bounds__(128) void aggregate_kernel(const float* __restrict__ x,
                                                        float* __restrict__ out) {
    int bid = blockIdx.x;
    int b  = bid >> 5;
    int t  = bid & 31;
    int w0 = (t & 1) * 32;
    int h0 = (t >> 1) * 4;
    int tid = threadIdx.x;
    int lw = tid & 31;
    int lh = tid >> 5;
    int h = h0 + lh, w = w0 + lw;

    __shared__ ull   as[2][ANT];       // [ev 374 | od 363]
    __shared__ float btap_s[288];
    __shared__ float bk_s[32];

    for (int i = tid; i < 288; i += 128) btap_s[i] = g_btap[i];
    if (tid < 32) bk_s[tid] = g_bk[tid];
    for (int i = tid; i < ANT; i += 128) { as[0][i] = 0ull; as[1][i] = 0ull; }

    // ---- one-time fill addressing ----
    int      goff[6];
    bool     vld[6];
    uint32_t sdst0[6], sdst1[6];
    uint32_t as0 = smem_u32(&as[0][0]), as1 = smem_u32(&as[1][0]);
#pragma unroll
    for (int it = 0; it < 6; it++) {
        int idx = tid + it * 128;
        int gr = 0, gc = 0;
        bool ok = idx < ANT;
        if (ok) {
            int r;
            if (idx < AEV) { r = idx / 34; gc = 2 * w0 - 2 + 2 * (idx - 34 * r); }
            else           { int j = idx - AEV; r = j / 33; gc = 2 * w0 - 1 + 2 * (j - 33 * r); }
            gr = 2 * h0 - 2 + r;
            ok = (gr >= 0) && (gr < 128) && (gc >= 0) && (gc < 128);
        }
        vld[it]  = ok;
        goff[it] = ok ? ((gr << 7) + gc) : 0;
        uint32_t off = ok ? (uint32_t)idx * 8 : 0u;
        sdst0[it] = as0 + off;
        sdst1[it] = as1 + off;
    }

    __syncthreads();

    // ---- softmax prologue: combine partial logits + biases ----
    ull m2[25];
    {
        float logit[25];
        size_t px = (size_t)(((b * 25) << 12)) + (h << 6) + w;
#pragma unroll
        for (int k = 0; k < 25; k++)
            logit[k] = g_part[px + (k << 12)] + g_part[(size_t)(8 * 25 * 4096) + px + (k << 12)]
                     + bk_s[k];
#pragma unroll
        for (int tap = 0; tap < 9; tap++) {
            int dy = tap / 3, dx = tap % 3;
            bool inb = (2 * h - 1 + dy >= 0) && (2 * w - 1 + dx >= 0) && (2 * w - 1 + dx < 128);
            if (inb) {
#pragma unroll
                for (int k = 0; k < 25; k++) logit[k] += btap_s[tap * 32 + k];
            }
        }
        float mx = logit[0];
#pragma unroll
        for (int k = 1; k < 25; k++) mx = fmaxf(mx, logit[k]);
        float sum = 0.f;
#pragma unroll
        for (int k = 0; k < 25; k++) { logit[k] = __expf(logit[k] - mx); sum += logit[k]; }
        float inv = 1.f / sum;
#pragma unroll
        for (int k = 0; k < 25; k++) { float m = logit[k] * inv; m2[k] = pack2(m, m); }
    }

    const float* xb = x + (size_t)b * 256 * 16384;
    auto fill = [&](int s, int cp) {
        const float* xc = xb + (size_t)(2 * cp) * 16384;
#pragma unroll
        for (int it = 0; it < 6; it++) {
            if (vld[it]) {
                uint32_t d = s ? sdst1[it] : sdst0[it];
                const float* p = xc + goff[it];
                cpa4(d,     p);
                cpa4(d + 4, p + 16384);
            }
        }
        CP_COMMIT();
    };

    float* ob = out + (((size_t)b * 256) << 12) + (h << 6) + w;
    fill(0, 0);
#pragma unroll 1
    for (int i = 0; i < NCP; i++) {
        int s = i & 1;
        if (i + 1 < NCP) { fill(s ^ 1, i + 1); cp_wait<1>(); }
        else             { cp_wait<0>(); }
        __syncthreads();

        ull acc_a = 0ull, acc_b = 0ull;
#pragma unroll
        for (int di = 0; di < 5; di++) {
            int lr = 2 * lh + di;
            ull x0 = as[s][lr * 34 + lw];
            ull x1 = as[s][AEV + lr * 33 + lw];
            ull x2 = as[s][lr * 34 + lw + 1];
            ull x3 = as[s][AEV + lr * 33 + lw + 1];
            ull x4 = as[s][lr * 34 + lw + 2];
            FMA2(acc_a, m2[di * 5 + 0], x0);
            FMA2(acc_b, m2[di * 5 + 1], x1);
            FMA2(acc_a, m2[di * 5 + 2], x2);
            FMA2(acc_b, m2[di * 5 + 3], x3);
            FMA2(acc_a, m2[di * 5 + 4], x4);
        }
        float a0, a1, b0, b1;
        unpack2(acc_a, a0, a1);
        unpack2(acc_b, b0, b1);
        float* po = ob + (((size_t)(2 * i)) << 12);
        po[0]    = a0 + b0;
        po[4096] = a1 + b1;
        __syncthreads();
    }
}

// ============================================================================
extern "C" void kernel_launch(void* const* d_in, const int* in_sizes, int n_in,
                              void* d_out, int out_size) {
    const float* x       = (const float*)d_in[0];
    const float* w_comp  = (const float*)d_in[1];
    const float* b_comp  = (const float*)d_in[2];
    const float* w_enc   = (const float*)d_in[3];
    const float* b_enc   = (const float*)d_in[4];
    const float* power_p = (const float*)d_in[5];
    float* out = (float*)d_out;

    prep_kernel<<<225, 256>>>(w_comp, b_comp, w_enc, b_enc, power_p);
    logits_kernel<<<256, 128>>>(x);
    aggregate_kernel<<<256, 128>>>(x, out);
}